// round 17
// baseline (speedup 1.0000x reference)
#include <cuda_runtime.h>
#include <cuda_bf16.h>
#include <cstdint>

namespace {
constexpr int B = 4, S = 2048, D = 64, KS = 4;
constexpr int MF = S / 16, KF = S / 16, NF = (B * D) / 8;  // 128, 128, 32
constexpr float SCALE = 0.022097086912079612f;  // 1/sqrt(2048)
constexpr float NEGBIG = -3.402823466e38f;
}

// ---- fragment-linear scratch: frag[(mf*KF+kf)*32 + lane] = uint4 ----------
__device__ uint4 g_faq_h[(size_t)MF * KF * 32];  // W_Q' hi  (a0,a1,a2,a3)
__device__ uint4 g_faq_l[(size_t)MF * KF * 32];  // W_Q' lo
__device__ uint4 g_fav_h[(size_t)MF * KF * 32];  // W_V  hi
__device__ uint4 g_fav_l[(size_t)MF * KF * 32];  // W_V  lo
__device__ uint4 g_fbx[(size_t)NF * KF * 32];    // x (k=s): (bh0,bh1,bl0,bl1)
// k3/k5 fragments: Q as A-frags (k=d), x as B-frags (n=j, k=d)
__device__ uint4 g_fq3h[(size_t)B * 128 * 4 * 32];
__device__ uint4 g_fq3l[(size_t)B * 128 * 4 * 32];
__device__ uint4 g_fx3[(size_t)B * 256 * 4 * 32];
// k5 fragments: V as B-frags (n=d, k=j), hi/lo packed
__device__ uint4 g_fv5[(size_t)B * 8 * 128 * 32];
__device__ float g_partM[B * 16 * S];
__device__ float g_partZ[B * 16 * S];
__device__ float g_colC[B * S];
__device__ float g_part[(size_t)KS * B * S * D];

// ---- helpers ---------------------------------------------------------------
__device__ __forceinline__ void hmma(float* c, const uint32_t* a, uint32_t b0, uint32_t b1) {
    asm volatile(
        "mma.sync.aligned.m16n8k16.row.col.f32.bf16.bf16.f32 "
        "{%0,%1,%2,%3}, {%4,%5,%6,%7}, {%8,%9}, {%0,%1,%2,%3};"
        : "+f"(c[0]), "+f"(c[1]), "+f"(c[2]), "+f"(c[3])
        : "r"(a[0]), "r"(a[1]), "r"(a[2]), "r"(a[3]), "r"(b0), "r"(b1));
}
__device__ __forceinline__ uint32_t bpack(__nv_bfloat16 e, __nv_bfloat16 o) {
    return (uint32_t)__bfloat16_as_ushort(e) | ((uint32_t)__bfloat16_as_ushort(o) << 16);
}
__device__ __forceinline__ void bsplit(float v, __nv_bfloat16& h, __nv_bfloat16& l) {
    h = __float2bfloat16(v);
    l = __float2bfloat16(v - __bfloat162float(h));
}
__device__ __forceinline__ void pack2hl(float a, float b, uint32_t& hi, uint32_t& lo) {
    __nv_bfloat16 ha, la, hb, lb;
    bsplit(a, ha, la); bsplit(b, hb, lb);
    hi = bpack(ha, hb); lo = bpack(la, lb);
}

// writes one row's 8 consecutive-k fp32 values into A-frag layout (hi+lo)
__device__ __forceinline__ void write_a_frags(const float* wv, int row, int tid,
                                              uint32_t* outh, uint32_t* outl) {
    const int mf = row >> 4, g = row & 7;
    const int reg = (((row & 15) < 8) ? 0 : 1) + ((tid & 1) ? 2 : 0);
    const int kf = tid >> 1;
    __nv_bfloat16 h[8], l[8];
#pragma unroll
    for (int j = 0; j < 8; j++) bsplit(wv[j], h[j], l[j]);
#pragma unroll
    for (int q = 0; q < 4; q++) {
        const size_t idx = (((size_t)mf * KF + kf) * 32 + g * 4 + q) * 4 + reg;
        outh[idx] = bpack(h[2 * q], h[2 * q + 1]);
        outl[idx] = bpack(l[2 * q], l[2 * q + 1]);
    }
}

// ---- k0x: x -> k2 B-frags (k=s) AND k3 B-frags (n=j, k=d) ------------------
__global__ __launch_bounds__(256) void k0_x(const float* __restrict__ x) {
    __shared__ float t[128][65];
    const int s0 = blockIdx.x * 128, b = blockIdx.y;
    const float* xb = x + (size_t)b * S * D;
    for (int i = threadIdx.x; i < 128 * 64; i += 256)
        t[i >> 6][i & 63] = xb[(size_t)(s0 + (i >> 6)) * D + (i & 63)];
    __syncthreads();
    const int w = threadIdx.x >> 5, lane = threadIdx.x & 31;
    const int g = lane >> 2, q = lane & 3;
    {   // k2 B-frags: n = b*64+d, k = s
        const int nf = b * 8 + w, d = w * 8 + g;
#pragma unroll
        for (int kfl = 0; kfl < 8; kfl++) {
            const int sb = kfl * 16;
            uint4 v;
            pack2hl(t[sb + 2 * q][d], t[sb + 2 * q + 1][d], v.x, v.z);
            pack2hl(t[sb + 8 + 2 * q][d], t[sb + 9 + 2 * q][d], v.y, v.w);
            g_fbx[((size_t)nf * KF + (s0 >> 4) + kfl) * 32 + lane] = v;
        }
    }
    // k3 B-frags: n = j (seq), k = d. warp handles 2 nf.
#pragma unroll
    for (int r = 0; r < 2; r++) {
        const int nfl = w * 2 + r;
        const int j = nfl * 8 + g;
#pragma unroll
        for (int kf = 0; kf < 4; kf++) {
            const int d0 = kf * 16 + 2 * q;
            uint4 v;
            pack2hl(t[j][d0], t[j][d0 + 1], v.x, v.z);
            pack2hl(t[j][d0 + 8], t[j][d0 + 9], v.y, v.w);
            g_fx3[((size_t)(b * 256 + (s0 >> 3) + nfl) * 4 + kf) * 32 + lane] = v;
        }
    }
}

// ---- k0w: W_V -> A-frag layout (one block per row) -------------------------
__global__ __launch_bounds__(256) void k0_wv(const float* __restrict__ WV) {
    const int row = blockIdx.x, tid = threadIdx.x;
    const float* src = WV + (size_t)row * S + tid * 8;
    float wv[8];
#pragma unroll
    for (int j = 0; j < 8; j++) wv[j] = src[j];
    write_a_frags(wv, row, tid, (uint32_t*)g_fav_h, (uint32_t*)g_fav_l);
}

// ---- k1: W_Q'[i,u] = sum_{t>=u} W_Q[i,t]/(t+1) -> A-frag layout ------------
__global__ __launch_bounds__(256) void k1_suffix(const float* __restrict__ WQ) {
    const int row = blockIdx.x, tid = threadIdx.x, base = tid * 8;
    const float* src = WQ + (size_t)row * S;
    float v[8], local = 0.f;
#pragma unroll
    for (int k = 0; k < 8; k++) { v[k] = src[base + k] / (float)(base + k + 1); local += v[k]; }
    float pre = local;
    const int lane = tid & 31, warp = tid >> 5;
#pragma unroll
    for (int off = 1; off < 32; off <<= 1) {
        float n = __shfl_up_sync(0xffffffff, pre, off);
        if (lane >= off) pre += n;
    }
    __shared__ float wsum[8], wpre[8], stot;
    if (lane == 31) wsum[warp] = pre;
    __syncthreads();
    if (tid == 0) {
        float acc = 0.f;
#pragma unroll
        for (int w = 0; w < 8; w++) { wpre[w] = acc; acc += wsum[w]; }
        stot = acc;
    }
    __syncthreads();
    float run = wpre[warp] + (pre - local);
    float wv[8];
#pragma unroll
    for (int k = 0; k < 8; k++) { wv[k] = stot - run; run += v[k]; }
    write_a_frags(wv, row, tid, (uint32_t*)g_faq_h, (uint32_t*)g_faq_l);
}

// ---- k2: HMMA GEMM, full-K, fused fragment epilogue (verified round 16) ----
__global__ __launch_bounds__(256, 2) void k2_hmma() {
    __shared__ float Vt[64][65];
    const int mt = blockIdx.x, b = blockIdx.y, mat = blockIdx.z;
    const int wid = threadIdx.x >> 5, lane = threadIdx.x & 31;
    const int wm = wid & 3, wn = wid >> 2;
    const int mf = mt * 4 + wm;
    const int nfb = b * 8 + wn * 4;

    const uint4* Ah = (mat ? g_fav_h : g_faq_h) + (size_t)mf * KF * 32 + lane;
    const uint4* Al = (mat ? g_fav_l : g_faq_l) + (size_t)mf * KF * 32 + lane;
    const uint4* Bp[4];
#pragma unroll
    for (int nt = 0; nt < 4; nt++)
        Bp[nt] = g_fbx + (size_t)(nfb + nt) * KF * 32 + lane;

    float acc[4][4];
#pragma unroll
    for (int t = 0; t < 4; t++)
#pragma unroll
        for (int c = 0; c < 4; c++) acc[t][c] = 0.f;

#pragma unroll 4
    for (int ks = 0; ks < KF; ks++) {
        const uint4 av = Ah[ks * 32];
        const uint4 lv = Al[ks * 32];
        const uint32_t ah[4] = {av.x, av.y, av.z, av.w};
        const uint32_t al[4] = {lv.x, lv.y, lv.z, lv.w};
#pragma unroll
        for (int nt = 0; nt < 4; nt++) {
            const uint4 bb = Bp[nt][ks * 32];
            hmma(acc[nt], ah, bb.x, bb.y);
            hmma(acc[nt], ah, bb.z, bb.w);
            hmma(acc[nt], al, bb.x, bb.y);
        }
    }
    const int g = lane >> 2, q = lane & 3;
    if (mat == 0) {
#pragma unroll
        for (int p = 0; p < 2; p++) {
            uint4 h, l;
            pack2hl(acc[2 * p][0], acc[2 * p][1], h.x, l.x);
            pack2hl(acc[2 * p][2], acc[2 * p][3], h.y, l.y);
            pack2hl(acc[2 * p + 1][0], acc[2 * p + 1][1], h.z, l.z);
            pack2hl(acc[2 * p + 1][2], acc[2 * p + 1][3], h.w, l.w);
            const size_t idx = ((size_t)(b * 128 + mf) * 4 + wn * 2 + p) * 32 + lane;
            g_fq3h[idx] = h;
            g_fq3l[idx] = l;
        }
    } else {
#pragma unroll
        for (int nt = 0; nt < 4; nt++) {
            const int dl = wn * 32 + nt * 8 + 2 * q;
            Vt[wm * 16 + g][dl] = acc[nt][0];
            Vt[wm * 16 + g][dl + 1] = acc[nt][1];
            Vt[wm * 16 + g + 8][dl] = acc[nt][2];
            Vt[wm * 16 + g + 8][dl + 1] = acc[nt][3];
        }
        __syncthreads();
        const int d = wid * 8 + g;
#pragma unroll
        for (int kfjl = 0; kfjl < 4; kfjl++) {
            const int sl = kfjl * 16 + 2 * q;
            uint4 v;
            pack2hl(Vt[sl][d], Vt[sl + 1][d], v.x, v.z);
            pack2hl(Vt[sl + 8][d], Vt[sl + 9][d], v.y, v.w);
            g_fv5[((size_t)(b * 8 + wid) * 128 + mt * 4 + kfjl) * 32 + lane] = v;
        }
    }
}

// ---- k3: HMMA masked scores -> column (m,z) partials ONLY (no score store) -
__global__ __launch_bounds__(256) void k3_hmma() {
    const int ic = blockIdx.x, jc = blockIdx.y, b = blockIdx.z;
    const int i0 = ic * 128, j0 = jc * 64;
    const int tid = threadIdx.x;
    if (i0 + 127 < j0) {
        if (tid < 64) {
            const size_t o = ((size_t)b * 16 + ic) * S + j0 + tid;
            g_partM[o] = -1e38f;
            g_partZ[o] = 0.f;
        }
        return;
    }
    __shared__ float St[128][68];
    __shared__ float red_m[16][64], red_z[16][64];
    const int wid = tid >> 5, lane = tid & 31;
    const int wm = wid & 3, wn = wid >> 2;
    const int g = lane >> 2, q = lane & 3;

    float acc[2][4][4];
#pragma unroll
    for (int mp = 0; mp < 2; mp++)
#pragma unroll
        for (int nt = 0; nt < 4; nt++)
#pragma unroll
            for (int c = 0; c < 4; c++) acc[mp][nt][c] = 0.f;

    const uint4* Ah = g_fq3h + ((size_t)(b * 128 + ic * 8 + wm * 2) * 4) * 32 + lane;
    const uint4* Al = g_fq3l + ((size_t)(b * 128 + ic * 8 + wm * 2) * 4) * 32 + lane;
    const uint4* Bf = g_fx3 + ((size_t)(b * 256 + jc * 8 + wn * 4) * 4) * 32 + lane;

#pragma unroll
    for (int kf = 0; kf < 4; kf++) {
        const uint4 a0 = Ah[kf * 32], a1 = Ah[(4 + kf) * 32];
        const uint4 l0 = Al[kf * 32], l1 = Al[(4 + kf) * 32];
        const uint32_t ah0[4] = {a0.x, a0.y, a0.z, a0.w};
        const uint32_t ah1[4] = {a1.x, a1.y, a1.z, a1.w};
        const uint32_t al0[4] = {l0.x, l0.y, l0.z, l0.w};
        const uint32_t al1[4] = {l1.x, l1.y, l1.z, l1.w};
#pragma unroll
        for (int nt = 0; nt < 4; nt++) {
            const uint4 bb = Bf[(nt * 4 + kf) * 32];
            hmma(acc[0][nt], ah0, bb.x, bb.y);
            hmma(acc[0][nt], ah0, bb.z, bb.w);
            hmma(acc[0][nt], al0, bb.x, bb.y);
            hmma(acc[1][nt], ah1, bb.x, bb.y);
            hmma(acc[1][nt], ah1, bb.z, bb.w);
            hmma(acc[1][nt], al1, bb.x, bb.y);
        }
    }
#pragma unroll
    for (int mp = 0; mp < 2; mp++)
#pragma unroll
        for (int nt = 0; nt < 4; nt++) {
            const int r0 = wm * 32 + mp * 16 + g, c0 = wn * 32 + nt * 8 + 2 * q;
            *(float2*)&St[r0][c0] = make_float2(acc[mp][nt][0], acc[mp][nt][1]);
            *(float2*)&St[r0 + 8][c0] = make_float2(acc[mp][nt][2], acc[mp][nt][3]);
        }
    __syncthreads();
    const int tx = tid & 15, ty = tid >> 4;
    float mc[4] = {-1e38f, -1e38f, -1e38f, -1e38f};
    float ov[8][4];
#pragma unroll
    for (int r = 0; r < 8; r++) {
        const int gi = i0 + ty * 8 + r;
        const float4 v = *(const float4*)&St[ty * 8 + r][tx * 4];
        const float vv[4] = {v.x, v.y, v.z, v.w};
#pragma unroll
        for (int c = 0; c < 4; c++) {
            const int gj = j0 + tx * 4 + c;
            const float o = (gi >= gj && vv[c] > 1.0f) ? vv[c] : NEGBIG;
            ov[r][c] = o;
            mc[c] = fmaxf(mc[c], o * SCALE);
        }
    }
    float zc[4] = {0.f, 0.f, 0.f, 0.f};
#pragma unroll
    for (int r = 0; r < 8; r++)
#pragma unroll
        for (int c = 0; c < 4; c++) zc[c] += __expf(ov[r][c] * SCALE - mc[c]);
#pragma unroll
    for (int c = 0; c < 4; c++) {
        red_m[ty][tx * 4 + c] = mc[c];
        red_z[ty][tx * 4 + c] = zc[c];
    }
    __syncthreads();
    if (tid < 64) {
        float m = -1e38f;
#pragma unroll
        for (int t = 0; t < 16; t++) m = fmaxf(m, red_m[t][tid]);
        float z = 0.f;
#pragma unroll
        for (int t = 0; t < 16; t++) z += red_z[t][tid] * __expf(red_m[t][tid] - m);
        const size_t o = ((size_t)b * 16 + ic) * S + j0 + tid;
        g_partM[o] = m;
        g_partZ[o] = z;
    }
}

// ---- k4b: reduce 16 partials -> colC[j] = m_j + log(z_j) -------------------
__global__ __launch_bounds__(256) void k4b_reduce() {
    const int j = blockIdx.x * 256 + threadIdx.x, b = blockIdx.y;
    float pm[16], pz[16];
#pragma unroll
    for (int i = 0; i < 16; i++) {
        pm[i] = g_partM[((size_t)b * 16 + i) * S + j];
        pz[i] = g_partZ[((size_t)b * 16 + i) * S + j];
    }
    float m = -1e38f;
#pragma unroll
    for (int i = 0; i < 16; i++) m = fmaxf(m, pm[i]);
    float z = 0.f;
#pragma unroll
    for (int i = 0; i < 16; i++) z += pz[i] * __expf(pm[i] - m);
    g_colC[b * S + j] = m + logf(z);
}

// ---- k5: recompute S in-register, exp -> P A-frags, P @ V ------------------
// S C-frag (two n8 tiles) is register-identical to P's A-frag: zero shuffles.
// grid (16 ic, KS sp, B). 8 warps: warp = 16 rows. jt = 16-j tile index.
__global__ __launch_bounds__(256) void k5_hmma() {
    const int ic = blockIdx.x, sp = blockIdx.y, b = blockIdx.z;
    const int i0 = ic * 128;
    const int wid = threadIdx.x >> 5, lane = threadIdx.x & 31;
    const int g = lane >> 2, q = lane & 3;
    const float* cC = g_colC + b * S;

    // Q A-frags for this warp's 16 rows, kept in registers
    const uint4* Qh = g_fq3h + ((size_t)(b * 128 + ic * 8 + wid) * 4) * 32 + lane;
    const uint4* Ql = g_fq3l + ((size_t)(b * 128 + ic * 8 + wid) * 4) * 32 + lane;
    uint4 qh[4], ql[4];
#pragma unroll
    for (int kf = 0; kf < 4; kf++) { qh[kf] = Qh[kf * 32]; ql[kf] = Ql[kf * 32]; }

    float acc[8][4];
#pragma unroll
    for (int nf = 0; nf < 8; nf++)
#pragma unroll
        for (int c = 0; c < 4; c++) acc[nf][c] = 0.f;

    const int r0g = i0 + wid * 16 + g;
    const int jtmax = ic * 8 + 7;
    for (int jt = sp; jt <= jtmax; jt += KS) {
        // --- recompute S for 16 rows x 16 j (two n8 tiles) ---
        float s0[4] = {0.f, 0.f, 0.f, 0.f}, s1[4] = {0.f, 0.f, 0.f, 0.f};
        const uint4* B0 = g_fx3 + ((size_t)(b * 256 + jt * 2) * 4) * 32 + lane;
        const uint4* B1 = g_fx3 + ((size_t)(b * 256 + jt * 2 + 1) * 4) * 32 + lane;
#pragma unroll
        for (int kf = 0; kf < 4; kf++) {
            const uint32_t ah[4] = {qh[kf].x, qh[kf].y, qh[kf].z, qh[kf].w};
            const uint32_t al[4] = {ql[kf].x, ql[kf].y, ql[kf].z, ql[kf].w};
            const uint4 b0 = B0[kf * 32];
            const uint4 b1 = B1[kf * 32];
            hmma(s0, ah, b0.x, b0.y);
            hmma(s0, ah, b0.z, b0.w);
            hmma(s0, al, b0.x, b0.y);
            hmma(s1, ah, b1.x, b1.y);
            hmma(s1, ah, b1.z, b1.w);
            hmma(s1, al, b1.x, b1.y);
        }
        // --- mask + exp -> P A-frags (in register) ---
        const int j0c = jt * 16 + 2 * q;
        const float2 cc0 = *(const float2*)(cC + j0c);
        const float2 cc1 = *(const float2*)(cC + j0c + 8);
        const float p0 = (r0g >= j0c && s0[0] > 1.f) ? __expf(s0[0] * SCALE - cc0.x) : 0.f;
        const float p1 = (r0g >= j0c + 1 && s0[1] > 1.f) ? __expf(s0[1] * SCALE - cc0.y) : 0.f;
        const float p2 = (r0g + 8 >= j0c && s0[2] > 1.f) ? __expf(s0[2] * SCALE - cc0.x) : 0.f;
        const float p3 = (r0g + 8 >= j0c + 1 && s0[3] > 1.f) ? __expf(s0[3] * SCALE - cc0.y) : 0.f;
        const float p4 = (r0g >= j0c + 8 && s1[0] > 1.f) ? __expf(s1[0] * SCALE - cc1.x) : 0.f;
        const float p5 = (r0g >= j0c + 9 && s1[1] > 1.f) ? __expf(s1[1] * SCALE - cc1.y) : 0.f;
        const float p6 = (r0g + 8 >= j0c + 8 && s1[2] > 1.f) ? __expf(s1[2] * SCALE - cc1.x) : 0.f;
        const float p7 = (r0g + 8 >= j0c + 9 && s1[3] > 1.f) ? __expf(s1[3] * SCALE - cc1.y) : 0.f;
        uint32_t ah[4], al[4];
        pack2hl(p0, p1, ah[0], al[0]);  // a0: row g,   k 2q..
        pack2hl(p2, p3, ah[1], al[1]);  // a1: row g+8, k 2q..
        pack2hl(p4, p5, ah[2], al[2]);  // a2: row g,   k 8+2q..
        pack2hl(p6, p7, ah[3], al[3]);  // a3: row g+8, k 8+2q..
        // --- P @ V over this k16 (= jt) ---
        const uint4* vf = g_fv5 + ((size_t)(b * 8) * 128 + jt) * 32 + lane;
#pragma unroll
        for (int nf = 0; nf < 8; nf++) {
            const uint4 v = vf[(size_t)nf * 128 * 32];
            hmma(acc[nf], ah, v.x, v.y);  // P_hi * V_hi
            hmma(acc[nf], ah, v.z, v.w);  // P_hi * V_lo
            hmma(acc[nf], al, v.x, v.y);  // P_lo * V_hi
        }
    }
    float* P = g_part + (size_t)(sp * B + b) * S * D;
#pragma unroll
    for (int nf = 0; nf < 8; nf++) {
        const int d0 = nf * 8 + (lane & 3) * 2;
        *(float2*)(P + (size_t)r0g * D + d0) = make_float2(acc[nf][0], acc[nf][1]);
        *(float2*)(P + (size_t)(r0g + 8) * D + d0) = make_float2(acc[nf][2], acc[nf][3]);
    }
}

// ---- k6: reduce KS split-K partials into d_out -----------------------------
__global__ __launch_bounds__(256) void k6_reduce(float* __restrict__ out) {
    const int idx = blockIdx.x * 256 + threadIdx.x;
    const float4* p = (const float4*)g_part;
    const size_t n4 = (size_t)B * S * D / 4;
    float4 a = p[idx];
#pragma unroll
    for (int sp = 1; sp < KS; sp++) {
        float4 q = p[sp * n4 + idx];
        a.x += q.x; a.y += q.y; a.z += q.z; a.w += q.w;
    }
    ((float4*)out)[idx] = a;
}

extern "C" void kernel_launch(void* const* d_in, const int* in_sizes, int n_in,
                              void* d_out, int out_size) {
    int xi = 0;
    for (int i = 0; i < n_in; i++)
        if (in_sizes[i] == B * S * D) { xi = i; break; }
    int o1 = -1, o2 = -1;
    for (int i = 0; i < n_in; i++)
        if (i != xi) { if (o1 < 0) o1 = i; else o2 = i; }
    const float* x = (const float*)d_in[xi];
    const float* WQ = (const float*)d_in[o1];
    const float* WV = (const float*)d_in[o2];

    k0_x<<<dim3(S / 128, B), 256>>>(x);
    k0_wv<<<S, 256>>>(WV);
    k1_suffix<<<S, 256>>>(WQ);
    k2_hmma<<<dim3(32, B, 2), 256>>>();
    k3_hmma<<<dim3(16, 32, B), 256>>>();
    k4b_reduce<<<dim3(S / 256, B), 256>>>();
    k5_hmma<<<dim3(16, KS, B), 256>>>();
    k6_reduce<<<(B * S * D / 4) / 256, 256>>>((float*)d_out);
}